// round 7
// baseline (speedup 1.0000x reference)
#include <cuda_runtime.h>
#include <cuda_bf16.h>
#include <cuda_fp16.h>
#include <cstdint>

#define NN 20000
#define NE 320000
#define NG 16
#define H1C 3
#define DC 128
#define F1C (H1C*DC)   // 384
#define NEG_SLOPE 0.2f

// ---------------- scratch (device globals; no allocation) ----------------
__device__ __half         g_f1[NN*F1C];    // layer-1 projected features (gather-only)
__device__ float          g_el1[NN*H1C];
__device__ float          g_er1[NN*H1C];
__device__ __nv_bfloat16  g_xhi[NN*DC];
__device__ __nv_bfloat16  g_xlo[NN*DC];
__device__ __nv_bfloat16  g_hhi[NN*F1C];
__device__ __nv_bfloat16  g_hlo[NN*F1C];
__device__ __nv_bfloat16  g_w1t_hi[F1C*DC];   // [384][128] = W1^T
__device__ __nv_bfloat16  g_w1t_lo[F1C*DC];
__device__ __nv_bfloat16  g_w2t_hi[DC*F1C];   // [128][384] = W2^T
__device__ __nv_bfloat16  g_w2t_lo[DC*F1C];
__device__ __half         g_f2[NN*DC];     // layer-2 projected features (gather-only)
__device__ float          g_el2[NN];
__device__ float          g_er2[NN];
__device__ int            g_deg[NN];
__device__ int            g_cur[NN];
__device__ int            g_off[NN+1];
__device__ int            g_csr_src[NE];
__device__ float          g_sums[NG*DC];
__device__ float          g_cnt[NG];

// ---------------- helpers ----------------
__device__ __forceinline__ uint32_t smem_u32(const void* p) {
    uint32_t a;
    asm("{ .reg .u64 t; cvta.to.shared.u64 t, %1; cvt.u32.u64 %0, t; }" : "=r"(a) : "l"(p));
    return a;
}
__device__ __forceinline__ void mma16816(float* c, const uint32_t* a, const uint32_t* b) {
    asm volatile(
        "mma.sync.aligned.m16n8k16.row.col.f32.bf16.bf16.f32 "
        "{%0,%1,%2,%3}, {%4,%5,%6,%7}, {%8,%9}, {%0,%1,%2,%3};"
        : "+f"(c[0]), "+f"(c[1]), "+f"(c[2]), "+f"(c[3])
        : "r"(a[0]), "r"(a[1]), "r"(a[2]), "r"(a[3]), "r"(b[0]), "r"(b[1]));
}
__device__ __forceinline__ void ldsm4(uint32_t* d, uint32_t addr) {
    asm volatile("ldmatrix.sync.aligned.m8n8.x4.shared.b16 {%0,%1,%2,%3}, [%4];"
                 : "=r"(d[0]), "=r"(d[1]), "=r"(d[2]), "=r"(d[3]) : "r"(addr));
}
__device__ __forceinline__ void cp16(uint32_t saddr, const void* g) {
    asm volatile("cp.async.cg.shared.global [%0], [%1], 16;" :: "r"(saddr), "l"(g));
}
__device__ __forceinline__ void cp16p(uint32_t saddr, const void* g, int szbytes) {
    asm volatile("cp.async.cg.shared.global [%0], [%1], 16, %2;"
                 :: "r"(saddr), "l"(g), "r"(szbytes));
}

// smem layout for GEMM: two 40960B stages; el/er at 81920.
#define STG 40960
#define S_ELER 81920
#define SM_GEMM (81920 + 1024)

// ---------------- small zero init ----------------
__global__ void k_zero_small() {
    int i = blockIdx.x * blockDim.x + threadIdx.x;
    if (i < NN) { g_deg[i] = 0; g_cur[i] = 0; }
    if (i < NG*DC) g_sums[i] = 0.f;
    if (i < NG) g_cnt[i] = 0.f;
}

// ---------------- CSR build (+ graph node counts) ----------------
__global__ void k_deg(const int* __restrict__ dst, const int* __restrict__ gids) {
    int i = blockIdx.x * blockDim.x + threadIdx.x;
    if (i < NE) atomicAdd(&g_deg[dst[i]], 1);
    if (i < NN) atomicAdd(&g_cnt[gids[i]], 1.f);
}
__global__ void k_scan() {
    __shared__ int partial[1024];
    int tid = threadIdx.x;
    const int CH = (NN + 1023) / 1024;   // 20
    int b0 = tid * CH;
    int s = 0;
    for (int i = 0; i < CH; i++) { int n = b0 + i; if (n < NN) s += g_deg[n]; }
    partial[tid] = s;
    __syncthreads();
    if (tid == 0) {
        int c = 0;
        for (int i = 0; i < 1024; i++) { int t = partial[i]; partial[i] = c; c += t; }
        g_off[NN] = c;
    }
    __syncthreads();
    int run = partial[tid];
    for (int i = 0; i < CH; i++) {
        int n = b0 + i;
        if (n < NN) { g_off[n] = run; run += g_deg[n]; }
    }
}
__global__ void k_scatter(const int* __restrict__ src, const int* __restrict__ dst) {
    int i = blockIdx.x * blockDim.x + threadIdx.x;
    if (i >= NE) return;
    int d = dst[i];
    int p = atomicAdd(&g_cur[d], 1);
    g_csr_src[g_off[d] + p] = src[i];
}

// ---------------- fp32 -> bf16 hi/lo split ----------------
__global__ void k_split(const float* __restrict__ A, __nv_bfloat16* __restrict__ hi,
                        __nv_bfloat16* __restrict__ lo, int n) {
    int i = 4 * (blockIdx.x * blockDim.x + threadIdx.x);
    if (i >= n) return;
    float4 v = *(const float4*)&A[i];
    __nv_bfloat16 h0 = __float2bfloat16(v.x), h1 = __float2bfloat16(v.y);
    __nv_bfloat16 h2 = __float2bfloat16(v.z), h3 = __float2bfloat16(v.w);
    __nv_bfloat16 l0 = __float2bfloat16(v.x - __bfloat162float(h0));
    __nv_bfloat16 l1 = __float2bfloat16(v.y - __bfloat162float(h1));
    __nv_bfloat16 l2 = __float2bfloat16(v.z - __bfloat162float(h2));
    __nv_bfloat16 l3 = __float2bfloat16(v.w - __bfloat162float(h3));
    *(__nv_bfloat162*)&hi[i]     = __halves2bfloat162(h0, h1);
    *(__nv_bfloat162*)&hi[i + 2] = __halves2bfloat162(h2, h3);
    *(__nv_bfloat162*)&lo[i]     = __halves2bfloat162(l0, l1);
    *(__nv_bfloat162*)&lo[i + 2] = __halves2bfloat162(l2, l3);
}

// ---------------- W [K,N] -> W^T [N,K] bf16 hi/lo ----------------
__global__ void k_tsplit(const float* __restrict__ W, __nv_bfloat16* __restrict__ hi,
                         __nv_bfloat16* __restrict__ lo, int K, int N) {
    int i = blockIdx.x * blockDim.x + threadIdx.x;
    if (i >= N * K) return;
    int n = i / K, k = i - n * K;
    float x = W[(size_t)k * N + n];
    __nv_bfloat16 h = __float2bfloat16(x);
    hi[i] = h;
    lo[i] = __float2bfloat16(x - __bfloat162float(h));
}

// ---------------- HMMA split-bf16 GEMM, cp.async double-buffered ----------------
// C[M,N] (fp16) = A[M,K] @ B^T, B stored [N,K]. Block 128x128, BK=32, 8 warps.
// Fused epilogue: el[n,h]=dot(C_row,al[h]), er likewise (fp32, h = blockIdx.x).
__global__ void __launch_bounds__(256, 1)
k_gemm_mma(const __nv_bfloat16* __restrict__ Ahi, const __nv_bfloat16* __restrict__ Alo,
           const __nv_bfloat16* __restrict__ Bhi, const __nv_bfloat16* __restrict__ Blo,
           __half* __restrict__ C, const float* __restrict__ al, const float* __restrict__ ar,
           float* __restrict__ el, float* __restrict__ er, int M, int N, int K, int H) {
    extern __shared__ char smem[];
    uint32_t sb = smem_u32(smem);
    int tid = threadIdx.x;
    int wid = tid >> 5, lane = tid & 31;
    int wm = wid >> 2, wn = wid & 3;
    int m0 = blockIdx.y * 128, n0 = blockIdx.x * 128;
    int h = blockIdx.x;

    float acc[4][4][4];
    #pragma unroll
    for (int i = 0; i < 4; i++)
        #pragma unroll
        for (int j = 0; j < 4; j++)
            #pragma unroll
            for (int q = 0; q < 4; q++) acc[i][j][q] = 0.f;

    int a_row = wm * 64 + (lane & 15);
    int a_coff = (lane >> 4) * 16;
    int b_row = wn * 32 + (lane & 7) + ((lane >> 4) & 1) * 8;
    int b_coff = ((lane >> 3) & 1) * 16;

    int nch = K >> 5;

    auto issue = [&](int c) {
        uint32_t stb = sb + (uint32_t)(c & 1) * STG;
        int k0 = c << 5;
        #pragma unroll
        for (int i = 0; i < 2; i++) {
            int ch = tid + i * 256;
            int r = ch >> 2, q = ch & 3;
            uint32_t so = stb + r * 80 + q * 16;
            int gm = m0 + r;
            int ok = (gm < M) ? 16 : 0;
            int rs = ok ? gm : 0;
            cp16p(so,         &Ahi[(size_t)rs * K + k0 + q * 8], ok);
            cp16p(so + 10240, &Alo[(size_t)rs * K + k0 + q * 8], ok);
            cp16(so + 20480, &Bhi[(size_t)(n0 + r) * K + k0 + q * 8]);
            cp16(so + 30720, &Blo[(size_t)(n0 + r) * K + k0 + q * 8]);
        }
        asm volatile("cp.async.commit_group;" ::: "memory");
    };

    issue(0);
    for (int c = 0; c < nch; c++) {
        if (c + 1 < nch) {
            issue(c + 1);
            asm volatile("cp.async.wait_group 1;" ::: "memory");
        } else {
            asm volatile("cp.async.wait_group 0;" ::: "memory");
        }
        __syncthreads();
        uint32_t stb = sb + (uint32_t)(c & 1) * STG;
        #pragma unroll
        for (int ks = 0; ks < 2; ks++) {
            uint32_t kb = ks * 32;
            uint32_t ahi[4][4], alo[4][4];
            #pragma unroll
            for (int mf = 0; mf < 4; mf++) {
                uint32_t ao = (a_row + mf * 16) * 80 + kb + a_coff;
                ldsm4(ahi[mf], stb + 0 + ao);
                ldsm4(alo[mf], stb + 10240 + ao);
            }
            uint32_t bhi[4][4], blo[4][4];
            #pragma unroll
            for (int j = 0; j < 2; j++) {
                uint32_t bo = (b_row + j * 16) * 80 + kb + b_coff;
                ldsm4(bhi[j * 2], stb + 20480 + bo);
                ldsm4(blo[j * 2], stb + 30720 + bo);
            }
            #pragma unroll
            for (int mf = 0; mf < 4; mf++) {
                #pragma unroll
                for (int nf = 0; nf < 4; nf++) {
                    const uint32_t* bh = &bhi[(nf >> 1) * 2][(nf & 1) * 2];
                    const uint32_t* bl = &blo[(nf >> 1) * 2][(nf & 1) * 2];
                    mma16816(acc[mf][nf], ahi[mf], bh);
                    mma16816(acc[mf][nf], ahi[mf], bl);
                    mma16816(acc[mf][nf], alo[mf], bh);
                }
            }
        }
        __syncthreads();
    }

    // ---- fused el/er ----
    float* el_s = (float*)(smem + S_ELER);
    float* er_s = el_s + 128;
    if (tid < 128) { el_s[tid] = 0.f; er_s[tid] = 0.f; }
    __syncthreads();
    {
        float a0[4], a1[4], r0[4], r1[4];
        #pragma unroll
        for (int nf = 0; nf < 4; nf++) {
            int gc = h * DC + wn * 32 + nf * 8 + (lane & 3) * 2;
            a0[nf] = al[gc]; a1[nf] = al[gc + 1];
            r0[nf] = ar[gc]; r1[nf] = ar[gc + 1];
        }
        #pragma unroll
        for (int mf = 0; mf < 4; mf++) {
            float s0e = 0.f, s0r = 0.f, s1e = 0.f, s1r = 0.f;
            #pragma unroll
            for (int nf = 0; nf < 4; nf++) {
                s0e += acc[mf][nf][0] * a0[nf] + acc[mf][nf][1] * a1[nf];
                s0r += acc[mf][nf][0] * r0[nf] + acc[mf][nf][1] * r1[nf];
                s1e += acc[mf][nf][2] * a0[nf] + acc[mf][nf][3] * a1[nf];
                s1r += acc[mf][nf][2] * r0[nf] + acc[mf][nf][3] * r1[nf];
            }
            int row = wm * 64 + mf * 16 + (lane >> 2);
            atomicAdd(&el_s[row], s0e);
            atomicAdd(&er_s[row], s0r);
            atomicAdd(&el_s[row + 8], s1e);
            atomicAdd(&er_s[row + 8], s1r);
        }
    }

    // ---- staged C store (convert to fp16) ----
    float* stage = (float*)smem;   // [128][33]
    #pragma unroll
    for (int cb = 0; cb < 4; cb++) {
        __syncthreads();
        if (wn == cb) {
            #pragma unroll
            for (int mf = 0; mf < 4; mf++) {
                int row = wm * 64 + mf * 16 + (lane >> 2);
                #pragma unroll
                for (int nf = 0; nf < 4; nf++) {
                    int col = nf * 8 + (lane & 3) * 2;
                    stage[row * 33 + col]       = acc[mf][nf][0];
                    stage[row * 33 + col + 1]   = acc[mf][nf][1];
                    stage[(row + 8) * 33 + col]     = acc[mf][nf][2];
                    stage[(row + 8) * 33 + col + 1] = acc[mf][nf][3];
                }
            }
        }
        __syncthreads();
        #pragma unroll
        for (int i = 0; i < 4; i++) {
            int idx = tid + i * 256;
            int row = idx >> 3, q = idx & 7;
            if (m0 + row < M) {
                const float* r = stage + row * 33 + q * 4;
                __half2 p0 = __floats2half2_rn(r[0], r[1]);
                __half2 p1 = __floats2half2_rn(r[2], r[3]);
                uint2 u;
                u.x = *(uint32_t*)&p0;
                u.y = *(uint32_t*)&p1;
                *(uint2*)&C[(size_t)(m0 + row) * N + n0 + cb * 32 + q * 4] = u;
            }
        }
    }
    __syncthreads();
    if (tid < 128 && m0 + tid < M) {
        el[(size_t)(m0 + tid) * H + h] = el_s[tid];
        er[(size_t)(m0 + tid) * H + h] = er_s[tid];
    }
}

// ---------------- softmax+agg core: register-resident softmax, fp16 gather ----------------
template <int H>
__device__ __forceinline__ void agg_core(const __half* __restrict__ f,
                                         const float* __restrict__ el, float erd,
                                         int off0, int deg, int h, int lane,
                                         float4& racc, float& den) {
    float4 acc = make_float4(0.f, 0.f, 0.f, 0.f);
    den = 0.f;
    if (deg <= 32) {
        int s = 0;
        float v = -3.0e38f;
        if (lane < deg) {
            s = g_csr_src[off0 + lane];
            v = el[s * H + h] + erd;
            v = v > 0.f ? v : NEG_SLOPE * v;
        }
        float mx = v;
        #pragma unroll
        for (int o = 16; o > 0; o >>= 1)
            mx = fmaxf(mx, __shfl_xor_sync(0xFFFFFFFFu, mx, o));
        float ex = (lane < deg) ? __expf(v - mx) : 0.f;
        float d = ex;
        #pragma unroll
        for (int o = 16; o > 0; o >>= 1)
            d += __shfl_xor_sync(0xFFFFFFFFu, d, o);
        den = d;
        #pragma unroll 4
        for (int j = 0; j < deg; j++) {
            float exj = __shfl_sync(0xFFFFFFFFu, ex, j);
            int   sj  = __shfl_sync(0xFFFFFFFFu, s, j);
            uint2 u = *(const uint2*)&f[(size_t)sj * (H * DC) + h * DC + lane * 4];
            float2 p0 = __half22float2(*(__half2*)&u.x);
            float2 p1 = __half22float2(*(__half2*)&u.y);
            acc.x = fmaf(exj, p0.x, acc.x);
            acc.y = fmaf(exj, p0.y, acc.y);
            acc.z = fmaf(exj, p1.x, acc.z);
            acc.w = fmaf(exj, p1.y, acc.w);
        }
    } else {
        float mx = -3.0e38f;
        for (int j = lane; j < deg; j += 32) {
            int s = g_csr_src[off0 + j];
            float v = el[s * H + h] + erd;
            v = v > 0.f ? v : NEG_SLOPE * v;
            mx = fmaxf(mx, v);
        }
        #pragma unroll
        for (int o = 16; o > 0; o >>= 1)
            mx = fmaxf(mx, __shfl_xor_sync(0xFFFFFFFFu, mx, o));
        for (int j = 0; j < deg; j++) {
            int s = g_csr_src[off0 + j];
            float v = el[s * H + h] + erd;
            v = v > 0.f ? v : NEG_SLOPE * v;
            float ex = __expf(v - mx);
            den += ex;
            uint2 u = *(const uint2*)&f[(size_t)s * (H * DC) + h * DC + lane * 4];
            float2 p0 = __half22float2(*(__half2*)&u.x);
            float2 p1 = __half22float2(*(__half2*)&u.y);
            acc.x = fmaf(ex, p0.x, acc.x);
            acc.y = fmaf(ex, p0.y, acc.y);
            acc.z = fmaf(ex, p1.x, acc.z);
            acc.w = fmaf(ex, p1.y, acc.w);
        }
    }
    racc = acc;
}

// ---------------- layer-1 agg: elu + bf16 hi/lo split output ----------------
__global__ void k_agg1(const __half* __restrict__ f, const float* __restrict__ el,
                       const float* __restrict__ er, const float* __restrict__ b,
                       __nv_bfloat16* __restrict__ outHi, __nv_bfloat16* __restrict__ outLo) {
    int w = (blockIdx.x * blockDim.x + threadIdx.x) >> 5;
    int lane = threadIdx.x & 31;
    if (w >= NN * H1C) return;
    int d = w / H1C, h = w - d * H1C;
    int off0 = g_off[d];
    int deg = g_off[d + 1] - off0;
    float erd = er[d * H1C + h];

    float4 acc; float den;
    agg_core<H1C>(f, el, erd, off0, deg, h, lane, acc, den);

    float inv = 1.f / (den > 0.f ? den : 1.f);
    float4 bb = *(const float4*)&b[h * DC + lane * 4];
    float4 r;
    r.x = acc.x * inv + bb.x;
    r.y = acc.y * inv + bb.y;
    r.z = acc.z * inv + bb.z;
    r.w = acc.w * inv + bb.w;
    r.x = r.x > 0.f ? r.x : expm1f(r.x);
    r.y = r.y > 0.f ? r.y : expm1f(r.y);
    r.z = r.z > 0.f ? r.z : expm1f(r.z);
    r.w = r.w > 0.f ? r.w : expm1f(r.w);

    size_t base = (size_t)d * F1C + h * DC + lane * 4;
    __nv_bfloat16 h0 = __float2bfloat16(r.x), h1 = __float2bfloat16(r.y);
    __nv_bfloat16 h2 = __float2bfloat16(r.z), h3 = __float2bfloat16(r.w);
    __nv_bfloat16 l0 = __float2bfloat16(r.x - __bfloat162float(h0));
    __nv_bfloat16 l1 = __float2bfloat16(r.y - __bfloat162float(h1));
    __nv_bfloat16 l2 = __float2bfloat16(r.z - __bfloat162float(h2));
    __nv_bfloat16 l3 = __float2bfloat16(r.w - __bfloat162float(h3));
    *(__nv_bfloat162*)&outHi[base]     = __halves2bfloat162(h0, h1);
    *(__nv_bfloat162*)&outHi[base + 2] = __halves2bfloat162(h2, h3);
    *(__nv_bfloat162*)&outLo[base]     = __halves2bfloat162(l0, l1);
    *(__nv_bfloat162*)&outLo[base + 2] = __halves2bfloat162(l2, l3);
}

// ---------------- layer-2 agg fused with graph mean-pool accumulation ----------------
__global__ void k_agg_pool(const __half* __restrict__ f, const float* __restrict__ el,
                           const float* __restrict__ er, const float* __restrict__ b,
                           const int* __restrict__ gids) {
    __shared__ float pacc[DC];
    __shared__ int uni;
    int tid = threadIdx.x;
    int wid = tid >> 5, lane = tid & 31;
    int d0 = blockIdx.x * 8;
    int d = d0 + wid;
    if (tid == 0) uni = (gids[d0] == gids[d0 + 7]) ? 1 : 0;
    if (tid < DC) pacc[tid] = 0.f;
    __syncthreads();

    int off0 = g_off[d];
    int deg = g_off[d + 1] - off0;
    float erd = er[d];

    float4 acc; float den;
    agg_core<1>(f, el, erd, off0, deg, 0, lane, acc, den);

    float inv = 1.f / (den > 0.f ? den : 1.f);
    float4 bb = *(const float4*)&b[lane * 4];
    float4 r;
    r.x = acc.x * inv + bb.x;
    r.y = acc.y * inv + bb.y;
    r.z = acc.z * inv + bb.z;
    r.w = acc.w * inv + bb.w;

    if (uni) {
        atomicAdd(&pacc[lane * 4 + 0], r.x);
        atomicAdd(&pacc[lane * 4 + 1], r.y);
        atomicAdd(&pacc[lane * 4 + 2], r.z);
        atomicAdd(&pacc[lane * 4 + 3], r.w);
    } else {
        int g = gids[d];
        atomicAdd(&g_sums[g * DC + lane * 4 + 0], r.x);
        atomicAdd(&g_sums[g * DC + lane * 4 + 1], r.y);
        atomicAdd(&g_sums[g * DC + lane * 4 + 2], r.z);
        atomicAdd(&g_sums[g * DC + lane * 4 + 3], r.w);
    }
    __syncthreads();
    if (uni && tid < DC) atomicAdd(&g_sums[gids[d0] * DC + tid], pacc[tid]);
}

// ---------------- output: relu((sums/cnt) @ linW + linb) ----------------
__global__ void k_out(const float* __restrict__ linW, const float* __restrict__ linb,
                      float* __restrict__ out) {
    int g = blockIdx.x;
    int c = threadIdx.x;
    __shared__ float hg[DC];
    float cnt = g_cnt[g];
    if (cnt < 1.f) cnt = 1.f;
    hg[c] = g_sums[g * DC + c] / cnt;
    __syncthreads();
    float acc = linb[c];
    #pragma unroll 8
    for (int k = 0; k < DC; k++)
        acc = fmaf(hg[k], linW[k * DC + c], acc);
    out[g * DC + c] = acc > 0.f ? acc : 0.f;
}

// ---------------- launch ----------------
extern "C" void kernel_launch(void* const* d_in, const int* in_sizes, int n_in,
                              void* d_out, int out_size) {
    const float* x    = (const float*)d_in[0];
    const int*   src  = (const int*)  d_in[1];
    const int*   dst  = (const int*)  d_in[2];
    const int*   gids = (const int*)  d_in[3];
    const float* W1   = (const float*)d_in[4];
    const float* al1  = (const float*)d_in[5];
    const float* ar1  = (const float*)d_in[6];
    const float* b1   = (const float*)d_in[7];
    const float* W2   = (const float*)d_in[8];
    const float* al2  = (const float*)d_in[9];
    const float* ar2  = (const float*)d_in[10];
    const float* b2   = (const float*)d_in[11];
    const float* linW = (const float*)d_in[12];
    const float* linb = (const float*)d_in[13];
    float* out = (float*)d_out;

    static cudaStream_t s1 = nullptr;
    static cudaEvent_t evFork = nullptr, evJoin = nullptr;
    if (!s1) {
        cudaStreamCreateWithFlags(&s1, cudaStreamNonBlocking);
        cudaEventCreateWithFlags(&evFork, cudaEventDisableTiming);
        cudaEventCreateWithFlags(&evJoin, cudaEventDisableTiming);
        cudaFuncSetAttribute(k_gemm_mma, cudaFuncAttributeMaxDynamicSharedMemorySize, SM_GEMM);
    }

    void *p_f1, *p_el1, *p_er1, *p_xhi, *p_xlo, *p_hhi, *p_hlo;
    void *p_w1h, *p_w1l, *p_w2h, *p_w2l;
    void *p_f2, *p_el2, *p_er2;
    cudaGetSymbolAddress(&p_f1,  g_f1);
    cudaGetSymbolAddress(&p_el1, g_el1);
    cudaGetSymbolAddress(&p_er1, g_er1);
    cudaGetSymbolAddress(&p_xhi, g_xhi);
    cudaGetSymbolAddress(&p_xlo, g_xlo);
    cudaGetSymbolAddress(&p_hhi, g_hhi);
    cudaGetSymbolAddress(&p_hlo, g_hlo);
    cudaGetSymbolAddress(&p_w1h, g_w1t_hi);
    cudaGetSymbolAddress(&p_w1l, g_w1t_lo);
    cudaGetSymbolAddress(&p_w2h, g_w2t_hi);
    cudaGetSymbolAddress(&p_w2l, g_w2t_lo);
    cudaGetSymbolAddress(&p_f2,  g_f2);
    cudaGetSymbolAddress(&p_el2, g_el2);
    cudaGetSymbolAddress(&p_er2, g_er2);

    // ---- fork: CSR branch on s1, GEMM-prep branch on stream 0 ----
    cudaEventRecord(evFork, 0);
    cudaStreamWaitEvent(s1, evFork, 0);

    // Branch A (s1): CSR build + pool-count init
    k_zero_small<<<(NN + 255) / 256, 256, 0, s1>>>();
    k_deg<<<(NE + 255) / 256, 256, 0, s1>>>(dst, gids);
    k_scan<<<1, 1024, 0, s1>>>();
    k_scatter<<<(NE + 255) / 256, 256, 0, s1>>>(src, dst);
    cudaEventRecord(evJoin, s1);

    // Branch B (stream 0): splits + GEMM1
    k_split<<<(NN * DC / 4 + 255) / 256, 256>>>(x, (__nv_bfloat16*)p_xhi,
                                                (__nv_bfloat16*)p_xlo, NN * DC);
    k_tsplit<<<(F1C * DC + 255) / 256, 256>>>(W1, (__nv_bfloat16*)p_w1h,
                                              (__nv_bfloat16*)p_w1l, DC, F1C);
    k_tsplit<<<(DC * F1C + 255) / 256, 256>>>(W2, (__nv_bfloat16*)p_w2h,
                                              (__nv_bfloat16*)p_w2l, F1C, DC);

    int mtiles = (NN + 127) / 128;   // 157
    {
        dim3 grid(F1C / 128, mtiles);
        k_gemm_mma<<<grid, 256, SM_GEMM>>>(
            (const __nv_bfloat16*)p_xhi, (const __nv_bfloat16*)p_xlo,
            (const __nv_bfloat16*)p_w1h, (const __nv_bfloat16*)p_w1l,
            (__half*)p_f1, al1, ar1, (float*)p_el1, (float*)p_er1,
            NN, F1C, DC, H1C);
    }

    // ---- join: agg1 needs CSR + GEMM1 ----
    cudaStreamWaitEvent(0, evJoin, 0);
    {
        int warps = NN * H1C;
        k_agg1<<<(warps * 32 + 255) / 256, 256>>>(
            (const __half*)p_f1, (const float*)p_el1, (const float*)p_er1, b1,
            (__nv_bfloat16*)p_hhi, (__nv_bfloat16*)p_hlo);
    }

    // ---- Layer 2 ----
    {
        dim3 grid(1, mtiles);
        k_gemm_mma<<<grid, 256, SM_GEMM>>>(
            (const __nv_bfloat16*)p_hhi, (const __nv_bfloat16*)p_hlo,
            (const __nv_bfloat16*)p_w2h, (const __nv_bfloat16*)p_w2l,
            (__half*)p_f2, al2, ar2, (float*)p_el2, (float*)p_er2,
            NN, DC, F1C, 1);
    }
    k_agg_pool<<<NN / 8, 256>>>((const __half*)p_f2, (const float*)p_el2,
                                (const float*)p_er2, b2, gids);

    // ---- readout ----
    k_out<<<NG, DC>>>(linW, linb, out);
}

// round 10
// speedup vs baseline: 1.4644x; 1.4644x over previous
#include <cuda_runtime.h>
#include <cuda_fp16.h>
#include <cstdint>

#define NN 20000
#define NE 320000
#define NG 16
#define H1C 3
#define DC 128
#define F1C (H1C*DC)   // 384
#define NEG_SLOPE 0.2f

// ---------------- scratch (device globals; no allocation) ----------------
__device__ __half g_f1[NN*F1C];     // layer-1 projected features (gather-only)
__device__ float  g_el1[NN*H1C];
__device__ float  g_er1[NN*H1C];
__device__ __half g_x16[NN*DC];     // fp16 input features
__device__ __half g_h16[NN*F1C];    // fp16 layer-1 output (GEMM2 A)
__device__ __half g_w1t[F1C*DC];    // [384][128] = W1^T fp16
__device__ __half g_w2t[DC*F1C];    // [128][384] = W2^T fp16
__device__ __half g_f2[NN*DC];      // layer-2 projected features
__device__ float  g_el2[NN];
__device__ float  g_er2[NN];
__device__ int    g_deg[NN];
__device__ int    g_cur[NN];
__device__ int    g_off[NN+1];
__device__ int    g_csr_src[NE];
__device__ float  g_sums[NG*DC];
__device__ float  g_cnt[NG];

// ---------------- helpers ----------------
__device__ __forceinline__ uint32_t smem_u32(const void* p) {
    uint32_t a;
    asm("{ .reg .u64 t; cvta.to.shared.u64 t, %1; cvt.u32.u64 %0, t; }" : "=r"(a) : "l"(p));
    return a;
}
__device__ __forceinline__ void mma16816h(float* c, const uint32_t* a, const uint32_t* b) {
    asm volatile(
        "mma.sync.aligned.m16n8k16.row.col.f32.f16.f16.f32 "
        "{%0,%1,%2,%3}, {%4,%5,%6,%7}, {%8,%9}, {%0,%1,%2,%3};"
        : "+f"(c[0]), "+f"(c[1]), "+f"(c[2]), "+f"(c[3])
        : "r"(a[0]), "r"(a[1]), "r"(a[2]), "r"(a[3]), "r"(b[0]), "r"(b[1]));
}
__device__ __forceinline__ void ldsm4(uint32_t* d, uint32_t addr) {
    asm volatile("ldmatrix.sync.aligned.m8n8.x4.shared.b16 {%0,%1,%2,%3}, [%4];"
                 : "=r"(d[0]), "=r"(d[1]), "=r"(d[2]), "=r"(d[3]) : "r"(addr));
}
__device__ __forceinline__ void cp16(uint32_t saddr, const void* g) {
    asm volatile("cp.async.cg.shared.global [%0], [%1], 16;" :: "r"(saddr), "l"(g));
}
__device__ __forceinline__ void cp16p(uint32_t saddr, const void* g, int szbytes) {
    asm volatile("cp.async.cg.shared.global [%0], [%1], 16, %2;"
                 :: "r"(saddr), "l"(g), "r"(szbytes));
}

// smem layout: stage = A(10240) + B(10240) = 20480B; two stages; el/er after.
#define STG 20480
#define S_ELER 40960
#define SM_GEMM (40960 + 1024)

// ---------------- small zero init ----------------
__global__ void k_zero_small() {
    int i = blockIdx.x * blockDim.x + threadIdx.x;
    if (i < NN) { g_deg[i] = 0; g_cur[i] = 0; }
    if (i < NG*DC) g_sums[i] = 0.f;
    if (i < NG) g_cnt[i] = 0.f;
}

// ---------------- CSR build (+ graph node counts) ----------------
__global__ void k_deg(const int* __restrict__ dst, const int* __restrict__ gids) {
    int i = blockIdx.x * blockDim.x + threadIdx.x;
    if (i < NE) atomicAdd(&g_deg[dst[i]], 1);
    if (i < NN) atomicAdd(&g_cnt[gids[i]], 1.f);
}
__global__ void k_scan() {
    __shared__ int partial[1024];
    int tid = threadIdx.x;
    const int CH = (NN + 1023) / 1024;   // 20
    int b0 = tid * CH;
    int s = 0;
    for (int i = 0; i < CH; i++) { int n = b0 + i; if (n < NN) s += g_deg[n]; }
    partial[tid] = s;
    __syncthreads();
    if (tid == 0) {
        int c = 0;
        for (int i = 0; i < 1024; i++) { int t = partial[i]; partial[i] = c; c += t; }
        g_off[NN] = c;
    }
    __syncthreads();
    int run = partial[tid];
    for (int i = 0; i < CH; i++) {
        int n = b0 + i;
        if (n < NN) { g_off[n] = run; run += g_deg[n]; }
    }
}
__global__ void k_scatter(const int* __restrict__ src, const int* __restrict__ dst) {
    int i = blockIdx.x * blockDim.x + threadIdx.x;
    if (i >= NE) return;
    int d = dst[i];
    int p = atomicAdd(&g_cur[d], 1);
    g_csr_src[g_off[d] + p] = src[i];
}

// ---------------- one prep kernel: x->fp16, W1^T->fp16, W2^T->fp16 ----------------
#define PREP_X (NN * DC / 4)            // float4 chunks
#define PREP_W (F1C * DC)               // elements per W
__global__ void k_prep(const float* __restrict__ x, const float* __restrict__ W1,
                       const float* __restrict__ W2) {
    int i = blockIdx.x * blockDim.x + threadIdx.x;
    if (i < PREP_X) {
        int e = i * 4;
        float4 v = *(const float4*)&x[e];
        __half2 p0 = __floats2half2_rn(v.x, v.y);
        __half2 p1 = __floats2half2_rn(v.z, v.w);
        uint2 u; u.x = *(uint32_t*)&p0; u.y = *(uint32_t*)&p1;
        *(uint2*)&g_x16[e] = u;
    } else if (i < PREP_X + PREP_W) {
        int j = i - PREP_X;            // w1t[n*DC + k] = W1[k*F1C + n]
        int n = j / DC, k = j - n * DC;
        g_w1t[j] = __float2half(W1[(size_t)k * F1C + n]);
    } else if (i < PREP_X + 2 * PREP_W) {
        int j = i - PREP_X - PREP_W;   // w2t[n*F1C + k] = W2[k*DC + n]
        int n = j / F1C, k = j - n * F1C;
        g_w2t[j] = __float2half(W2[(size_t)k * DC + n]);
    }
}

// ---------------- fp16 HMMA GEMM, cp.async double-buffered ----------------
// C[M,N] (fp16) = A[M,K] @ B^T, B stored [N,K] fp16. Block 128x128, BK=32, 8 warps.
// Fused epilogue: el[n,h]=dot(C_row,al[h]), er likewise (fp32, h = blockIdx.x).
__global__ void __launch_bounds__(256, 2)
k_gemm_mma(const __half* __restrict__ A, const __half* __restrict__ B,
           __half* __restrict__ C, const float* __restrict__ al, const float* __restrict__ ar,
           float* __restrict__ el, float* __restrict__ er, int M, int N, int K, int H) {
    extern __shared__ char smem[];
    uint32_t sb = smem_u32(smem);
    int tid = threadIdx.x;
    int wid = tid >> 5, lane = tid & 31;
    int wm = wid >> 2, wn = wid & 3;
    int m0 = blockIdx.y * 128, n0 = blockIdx.x * 128;
    int h = blockIdx.x;

    float acc[4][4][4];
    #pragma unroll
    for (int i = 0; i < 4; i++)
        #pragma unroll
        for (int j = 0; j < 4; j++)
            #pragma unroll
            for (int q = 0; q < 4; q++) acc[i][j][q] = 0.f;

    int a_row = wm * 64 + (lane & 15);
    int a_coff = (lane >> 4) * 16;
    int b_row = wn * 32 + (lane & 7) + ((lane >> 4) & 1) * 8;
    int b_coff = ((lane >> 3) & 1) * 16;

    int nch = K >> 5;

    auto issue = [&](int c) {
        uint32_t stb = sb + (uint32_t)(c & 1) * STG;
        int k0 = c << 5;
        #pragma unroll
        for (int i = 0; i < 2; i++) {
            int ch = tid + i * 256;
            int r = ch >> 2, q = ch & 3;
            uint32_t so = stb + r * 80 + q * 16;
            int gm = m0 + r;
            int ok = (gm < M) ? 16 : 0;
            int rs = ok ? gm : 0;
            cp16p(so, &A[(size_t)rs * K + k0 + q * 8], ok);
            cp16(so + 10240, &B[(size_t)(n0 + r) * K + k0 + q * 8]);
        }
        asm volatile("cp.async.commit_group;" ::: "memory");
    };

    issue(0);
    for (int c = 0; c < nch; c++) {
        if (c + 1 < nch) {
            issue(c + 1);
            asm volatile("cp.async.wait_group 1;" ::: "memory");
        } else {
            asm volatile("cp.async.wait_group 0;" ::: "memory");
        }
        __syncthreads();
        uint32_t stb = sb + (uint32_t)(c & 1) * STG;
        #pragma unroll
        for (int ks = 0; ks < 2; ks++) {
            uint32_t kb = ks * 32;
            uint32_t af[4][4];
            #pragma unroll
            for (int mf = 0; mf < 4; mf++) {
                uint32_t ao = (a_row + mf * 16) * 80 + kb + a_coff;
                ldsm4(af[mf], stb + ao);
            }
            uint32_t bf[4][4];
            #pragma unroll
            for (int j = 0; j < 2; j++) {
                uint32_t bo = (b_row + j * 16) * 80 + kb + b_coff;
                ldsm4(bf[j * 2], stb + 10240 + bo);
            }
            #pragma unroll
            for (int mf = 0; mf < 4; mf++) {
                #pragma unroll
                for (int nf = 0; nf < 4; nf++) {
                    const uint32_t* b2p = &bf[(nf >> 1) * 2][(nf & 1) * 2];
                    mma16816h(acc[mf][nf], af[mf], b2p);
                }
            }
        }
        __syncthreads();
    }

    // ---- fused el/er ----
    float* el_s = (float*)(smem + S_ELER);
    float* er_s = el_s + 128;
    if (tid < 128) { el_s[tid] = 0.f; er_s[tid] = 0.f; }
    __syncthreads();
    {
        float a0[4], a1[4], r0[4], r1[4];
        #pragma unroll
        for (int nf = 0; nf < 4; nf++) {
            int gc = h * DC + wn * 32 + nf * 8 + (lane & 3) * 2;
            a0[nf] = al[gc]; a1[nf] = al[gc + 1];
            r0[nf] = ar[gc]; r1[nf] = ar[gc + 1];
        }
        #pragma unroll
        for (int mf = 0; mf < 4; mf++) {
            float s0e = 0.f, s0r = 0.f, s1e = 0.f, s1r = 0.f;
            #pragma unroll
            for (int nf = 0; nf < 4; nf++) {
                s0e += acc[mf][nf][0] * a0[nf] + acc[mf][nf][1] * a1[nf];
                s0r += acc[mf][nf][0] * r0[nf] + acc[mf][nf][1] * r1[nf];
                s1e += acc[mf][nf][2] * a0[nf] + acc[mf][nf][3] * a1[nf];
                s1r += acc[mf][nf][2] * r0[nf] + acc[mf][nf][3] * r1[nf];
            }
            int row = wm * 64 + mf * 16 + (lane >> 2);
            atomicAdd(&el_s[row], s0e);
            atomicAdd(&er_s[row], s0r);
            atomicAdd(&el_s[row + 8], s1e);
            atomicAdd(&er_s[row + 8], s1r);
        }
    }

    // ---- staged C store (fp16) ----
    float* stage = (float*)smem;   // [128][33]
    #pragma unroll
    for (int cb = 0; cb < 4; cb++) {
        __syncthreads();
        if (wn == cb) {
            #pragma unroll
            for (int mf = 0; mf < 4; mf++) {
                int row = wm * 64 + mf * 16 + (lane >> 2);
                #pragma unroll
                for (int nf = 0; nf < 4; nf++) {
                    int col = nf * 8 + (lane & 3) * 2;
                    stage[row * 33 + col]       = acc[mf][nf][0];
                    stage[row * 33 + col + 1]   = acc[mf][nf][1];
                    stage[(row + 8) * 33 + col]     = acc[mf][nf][2];
                    stage[(row + 8) * 33 + col + 1] = acc[mf][nf][3];
                }
            }
        }
        __syncthreads();
        #pragma unroll
        for (int i = 0; i < 4; i++) {
            int idx = tid + i * 256;
            int row = idx >> 3, q = idx & 7;
            if (m0 + row < M) {
                const float* r = stage + row * 33 + q * 4;
                __half2 p0 = __floats2half2_rn(r[0], r[1]);
                __half2 p1 = __floats2half2_rn(r[2], r[3]);
                uint2 u;
                u.x = *(uint32_t*)&p0;
                u.y = *(uint32_t*)&p1;
                *(uint2*)&C[(size_t)(m0 + row) * N + n0 + cb * 32 + q * 4] = u;
            }
        }
    }
    __syncthreads();
    if (tid < 128 && m0 + tid < M) {
        el[(size_t)(m0 + tid) * H + h] = el_s[tid];
        er[(size_t)(m0 + tid) * H + h] = er_s[tid];
    }
}

// ---------------- softmax+agg core: register-resident softmax, fp16 gather ----------------
template <int H>
__device__ __forceinline__ void agg_core(const __half* __restrict__ f,
                                         const float* __restrict__ el, float erd,
                                         int off0, int deg, int h, int lane,
                                         float4& racc, float& den) {
    float4 acc = make_float4(0.f, 0.f, 0.f, 0.f);
    den = 0.f;
    if (deg <= 32) {
        int s = 0;
        float v = -3.0e38f;
        if (lane < deg) {
            s = g_csr_src[off0 + lane];
            v = el[s * H + h] + erd;
            v = v > 0.f ? v : NEG_SLOPE * v;
        }
        float mx = v;
        #pragma unroll
        for (int o = 16; o > 0; o >>= 1)
            mx = fmaxf(mx, __shfl_xor_sync(0xFFFFFFFFu, mx, o));
        float ex = (lane < deg) ? __expf(v - mx) : 0.f;
        float d = ex;
        #pragma unroll
        for (int o = 16; o > 0; o >>= 1)
            d += __shfl_xor_sync(0xFFFFFFFFu, d, o);
        den = d;
        #pragma unroll 4
        for (int j = 0; j < deg; j++) {
            float exj = __shfl_sync(0xFFFFFFFFu, ex, j);
            int   sj  = __shfl_sync(0xFFFFFFFFu, s, j);
            uint2 u = *(const uint2*)&f[(size_t)sj * (H * DC) + h * DC + lane * 4];
            float2 p0 = __half22float2(*(__half2*)&u.x);
            float2 p1 = __half22float2(*(__half2*)&u.y);
            acc.x = fmaf(exj, p0.x, acc.x);
            acc.y = fmaf(exj, p0.y, acc.y);
            acc.z = fmaf(exj, p1.x, acc.z);
            acc.w = fmaf(exj, p1.y, acc.w);
        }
    } else {
        float mx = -3.0e38f;
        for (int j = lane; j < deg; j += 32) {
            int s = g_csr_src[off0 + j];
            float v = el[s * H + h] + erd;
            v = v > 0.f ? v : NEG_SLOPE * v;
            mx = fmaxf(mx, v);
        }
        #pragma unroll
        for (int o = 16; o > 0; o >>= 1)
            mx = fmaxf(mx, __shfl_xor_sync(0xFFFFFFFFu, mx, o));
        for (int j = 0; j < deg; j++) {
            int s = g_csr_src[off0 + j];
            float v = el[s * H + h] + erd;
            v = v > 0.f ? v : NEG_SLOPE * v;
            float ex = __expf(v - mx);
            den += ex;
            uint2 u = *(const uint2*)&f[(size_t)s * (H * DC) + h * DC + lane * 4];
            float2 p0 = __half22float2(*(__half2*)&u.x);
            float2 p1 = __half22float2(*(__half2*)&u.y);
            acc.x = fmaf(ex, p0.x, acc.x);
            acc.y = fmaf(ex, p0.y, acc.y);
            acc.z = fmaf(ex, p1.x, acc.z);
            acc.w = fmaf(ex, p1.y, acc.w);
        }
    }
    racc = acc;
}

// ---------------- layer-1 agg: elu + fp16 output ----------------
__global__ void k_agg1(const __half* __restrict__ f, const float* __restrict__ el,
                       const float* __restrict__ er, const float* __restrict__ b,
                       __half* __restrict__ outH) {
    int w = (blockIdx.x * blockDim.x + threadIdx.x) >> 5;
    int lane = threadIdx.x & 31;
    if (w >= NN * H1C) return;
    int d = w / H1C, h = w - d * H1C;
    int off0 = g_off[d];
    int deg = g_off[d + 1] - off0;
    float erd = er[d * H1C + h];

    float4 acc; float den;
    agg_core<H1C>(f, el, erd, off0, deg, h, lane, acc, den);

    float inv = 1.f / (den > 0.f ? den : 1.f);
    float4 bb = *(const float4*)&b[h * DC + lane * 4];
    float4 r;
    r.x = acc.x * inv + bb.x;
    r.y = acc.y * inv + bb.y;
    r.z = acc.z * inv + bb.z;
    r.w = acc.w * inv + bb.w;
    r.x = r.x > 0.f ? r.x : expm1f(r.x);
    r.y = r.y > 0.f ? r.y : expm1f(r.y);
    r.z = r.z > 0.f ? r.z : expm1f(r.z);
    r.w = r.w > 0.f ? r.w : expm1f(r.w);

    size_t base = (size_t)d * F1C + h * DC + lane * 4;
    __half2 p0 = __floats2half2_rn(r.x, r.y);
    __half2 p1 = __floats2half2_rn(r.z, r.w);
    uint2 u; u.x = *(uint32_t*)&p0; u.y = *(uint32_t*)&p1;
    *(uint2*)&outH[base] = u;
}

// ---------------- layer-2 agg fused with graph mean-pool accumulation ----------------
__global__ void k_agg_pool(const __half* __restrict__ f, const float* __restrict__ el,
                           const float* __restrict__ er, const float* __restrict__ b,
                           const int* __restrict__ gids) {
    __shared__ float pacc[DC];
    __shared__ int uni;
    int tid = threadIdx.x;
    int wid = tid >> 5, lane = tid & 31;
    int d0 = blockIdx.x * 8;
    int d = d0 + wid;
    if (tid == 0) uni = (gids[d0] == gids[d0 + 7]) ? 1 : 0;
    if (tid < DC) pacc[tid] = 0.f;
    __syncthreads();

    int off0 = g_off[d];
    int deg = g_off[d + 1] - off0;
    float erd = er[d];

    float4 acc; float den;
    agg_core<1>(f, el, erd, off0, deg, 0, lane, acc, den);

    float inv = 1.f / (den > 0.f ? den : 1.f);
    float4 bb = *(const float4*)&b[lane * 4];
    float4 r;
    r.x = acc.x * inv + bb.x;
    r.y = acc.y * inv + bb.y;
    r.z = acc.z * inv + bb.z;
    r.w = acc.w * inv + bb.w;

    if (uni) {
        atomicAdd(&pacc[lane * 4 + 0], r.x);
        atomicAdd(&pacc[lane * 4 + 1], r.y);
        atomicAdd(&pacc[lane * 4 + 2], r.z);
        atomicAdd(&pacc[lane * 4 + 3], r.w);
    } else {
        int g = gids[d];
        atomicAdd(&g_sums[g * DC + lane * 4 + 0], r.x);
        atomicAdd(&g_sums[g * DC + lane * 4 + 1], r.y);
        atomicAdd(&g_sums[g * DC + lane * 4 + 2], r.z);
        atomicAdd(&g_sums[g * DC + lane * 4 + 3], r.w);
    }
    __syncthreads();
    if (uni && tid < DC) atomicAdd(&g_sums[gids[d0] * DC + tid], pacc[tid]);
}

// ---------------- output: relu((sums/cnt) @ linW + linb) ----------------
__global__ void k_out(const float* __restrict__ linW, const float* __restrict__ linb,
                      float* __restrict__ out) {
    int g = blockIdx.x;
    int c = threadIdx.x;
    __shared__ float hg[DC];
    float cnt = g_cnt[g];
    if (cnt < 1.f) cnt = 1.f;
    hg[c] = g_sums[g * DC + c] / cnt;
    __syncthreads();
    float acc = linb[c];
    #pragma unroll 8
    for (int k = 0; k < DC; k++)
        acc = fmaf(hg[k], linW[k * DC + c], acc);
    out[g * DC + c] = acc > 0.f ? acc : 0.f;
}

// ---------------- launch ----------------
extern "C" void kernel_launch(void* const* d_in, const int* in_sizes, int n_in,
                              void* d_out, int out_size) {
    const float* x    = (const float*)d_in[0];
    const int*   src  = (const int*)  d_in[1];
    const int*   dst  = (const int*)  d_in[2];
    const int*   gids = (const int*)  d_in[3];
    const float* W1   = (const float*)d_in[4];
    const float* al1  = (const float*)d_in[5];
    const float* ar1  = (const float*)d_in[6];
    const float* b1   = (const float*)d_in[7];
    const float* W2   = (const float*)d_in[8];
    const float* al2  = (const float*)d_in[9];
    const float* ar2  = (const float*)d_in[10];
    const float* b2   = (const float*)d_in[11];
    const float* linW = (const float*)d_in[12];
    const float* linb = (const float*)d_in[13];
    float* out = (float*)d_out;

    static cudaStream_t s1 = nullptr;
    static cudaEvent_t evFork = nullptr, evJoin = nullptr;
    if (!s1) {
        cudaStreamCreateWithFlags(&s1, cudaStreamNonBlocking);
        cudaEventCreateWithFlags(&evFork, cudaEventDisableTiming);
        cudaEventCreateWithFlags(&evJoin, cudaEventDisableTiming);
        cudaFuncSetAttribute(k_gemm_mma, cudaFuncAttributeMaxDynamicSharedMemorySize, SM_GEMM);
    }

    void *p_f1, *p_el1, *p_er1, *p_x16, *p_h16, *p_w1t, *p_w2t;
    void *p_f2, *p_el2, *p_er2;
    cudaGetSymbolAddress(&p_f1,  g_f1);
    cudaGetSymbolAddress(&p_el1, g_el1);
    cudaGetSymbolAddress(&p_er1, g_er1);
    cudaGetSymbolAddress(&p_x16, g_x16);
    cudaGetSymbolAddress(&p_h16, g_h16);
    cudaGetSymbolAddress(&p_w1t, g_w1t);
    cudaGetSymbolAddress(&p_w2t, g_w2t);
    cudaGetSymbolAddress(&p_f2,  g_f2);
    cudaGetSymbolAddress(&p_el2, g_el2);
    cudaGetSymbolAddress(&p_er2, g_er2);

    // ---- fork: CSR branch on s1, GEMM-prep branch on stream 0 ----
    cudaEventRecord(evFork, 0);
    cudaStreamWaitEvent(s1, evFork, 0);

    // Branch A (s1): CSR build + pool-count init
    k_zero_small<<<(NN + 255) / 256, 256, 0, s1>>>();
    k_deg<<<(NE + 255) / 256, 256, 0, s1>>>(dst, gids);
    k_scan<<<1, 1024, 0, s1>>>();
    k_scatter<<<(NE + 255) / 256, 256, 0, s1>>>(src, dst);
    cudaEventRecord(evJoin, s1);

    // Branch B (stream 0): prep + GEMM1
    {
        int total = PREP_X + 2 * PREP_W;
        k_prep<<<(total + 255) / 256, 256>>>(x, W1, W2);
    }

    int mtiles = (NN + 127) / 128;   // 157
    {
        dim3 grid(F1C / 128, mtiles);
        k_gemm_mma<<<grid, 256, SM_GEMM>>>(
            (const __half*)p_x16, (const __half*)p_w1t,
            (__half*)p_f1, al1, ar1, (float*)p_el1, (float*)p_er1,
            NN, F1C, DC, H1C);
    }

    // ---- join: agg1 needs CSR + GEMM1 ----
    cudaStreamWaitEvent(0, evJoin, 0);
    {
        int warps = NN * H1C;
        k_agg1<<<(warps * 32 + 255) / 256, 256>>>(
            (const __half*)p_f1, (const float*)p_el1, (const float*)p_er1, b1,
            (__half*)p_h16);
    }

    // ---- Layer 2 ----
    {
        dim3 grid(1, mtiles);
        k_gemm_mma<<<grid, 256, SM_GEMM>>>(
            (const __half*)p_h16, (const __half*)p_w2t,
            (__half*)p_f2, al2, ar2, (float*)p_el2, (float*)p_er2,
            NN, DC, F1C, 1);
    }
    k_agg_pool<<<NN / 8, 256>>>((const __half*)p_f2, (const float*)p_el2,
                                (const float*)p_er2, b2, gids);

    // ---- readout ----
    k_out<<<NG, DC>>>(linW, linb, out);
}

// round 11
// speedup vs baseline: 1.6123x; 1.1010x over previous
#include <cuda_runtime.h>
#include <cuda_fp16.h>
#include <cstdint>

#define NN 20000
#define NE 320000
#define NG 16
#define H1C 3
#define DC 128
#define F1C (H1C*DC)   // 384
#define NEG_SLOPE 0.2f

// ---------------- scratch (device globals; no allocation) ----------------
__device__ __half g_f1[NN*F1C];     // layer-1 projected features (gather-only)
__device__ float  g_el1[NN*4];      // stride-4 (heads 0..2 + pad)
__device__ float  g_er1[NN*4];
__device__ __half g_x16[NN*DC];     // fp16 input features
__device__ __half g_h16[NN*F1C];    // fp16 layer-1 output (GEMM2 A)
__device__ __half g_w1t[F1C*DC];    // [384][128] = W1^T fp16
__device__ __half g_w2t[DC*F1C];    // [128][384] = W2^T fp16
__device__ __half g_f2[NN*DC];      // layer-2 projected features
__device__ float  g_el2[NN];
__device__ float  g_er2[NN];
__device__ int    g_deg[NN];
__device__ int    g_cur[NN];
__device__ int    g_off[NN+1];
__device__ int    g_csr_src[NE];
__device__ float  g_sums[NG*DC];
__device__ float  g_cnt[NG];

// ---------------- helpers ----------------
__device__ __forceinline__ uint32_t smem_u32(const void* p) {
    uint32_t a;
    asm("{ .reg .u64 t; cvta.to.shared.u64 t, %1; cvt.u32.u64 %0, t; }" : "=r"(a) : "l"(p));
    return a;
}
__device__ __forceinline__ void mma16816h(float* c, const uint32_t* a, const uint32_t* b) {
    asm volatile(
        "mma.sync.aligned.m16n8k16.row.col.f32.f16.f16.f32 "
        "{%0,%1,%2,%3}, {%4,%5,%6,%7}, {%8,%9}, {%0,%1,%2,%3};"
        : "+f"(c[0]), "+f"(c[1]), "+f"(c[2]), "+f"(c[3])
        : "r"(a[0]), "r"(a[1]), "r"(a[2]), "r"(a[3]), "r"(b[0]), "r"(b[1]));
}
__device__ __forceinline__ void ldsm4(uint32_t* d, uint32_t addr) {
    asm volatile("ldmatrix.sync.aligned.m8n8.x4.shared.b16 {%0,%1,%2,%3}, [%4];"
                 : "=r"(d[0]), "=r"(d[1]), "=r"(d[2]), "=r"(d[3]) : "r"(addr));
}
__device__ __forceinline__ void cp16(uint32_t saddr, const void* g) {
    asm volatile("cp.async.cg.shared.global [%0], [%1], 16;" :: "r"(saddr), "l"(g));
}
__device__ __forceinline__ void cp16p(uint32_t saddr, const void* g, int szbytes) {
    asm volatile("cp.async.cg.shared.global [%0], [%1], 16, %2;"
                 :: "r"(saddr), "l"(g), "r"(szbytes));
}

// smem layout: stage = A(10240) + B(10240) = 20480B; two stages; el/er after.
#define STG 20480
#define S_ELER 40960
#define SM_GEMM (40960 + 1024)

// ---------------- small zero init ----------------
__global__ void k_zero_small() {
    int i = blockIdx.x * blockDim.x + threadIdx.x;
    if (i < NN) { g_deg[i] = 0; g_cur[i] = 0; }
    if (i < NG*DC) g_sums[i] = 0.f;
    if (i < NG) g_cnt[i] = 0.f;
}

// ---------------- CSR build (+ graph node counts) ----------------
__global__ void k_deg(const int* __restrict__ dst, const int* __restrict__ gids) {
    int i = blockIdx.x * blockDim.x + threadIdx.x;
    if (i < NE) atomicAdd(&g_deg[dst[i]], 1);
    if (i < NN) atomicAdd(&g_cnt[gids[i]], 1.f);
}

// 1024 threads, shfl hierarchical scan
__global__ void k_scan() {
    __shared__ int warpsum[32];
    int tid = threadIdx.x;
    int lane = tid & 31, w = tid >> 5;
    const int CH = (NN + 1023) / 1024;   // 20
    int b0 = tid * CH;
    int s = 0;
    for (int i = 0; i < CH; i++) { int n = b0 + i; if (n < NN) s += g_deg[n]; }
    int v = s;
    #pragma unroll
    for (int o = 1; o < 32; o <<= 1) {
        int t = __shfl_up_sync(0xFFFFFFFFu, v, o);
        if (lane >= o) v += t;
    }
    if (lane == 31) warpsum[w] = v;
    __syncthreads();
    if (w == 0) {
        int ws = warpsum[lane];
        #pragma unroll
        for (int o = 1; o < 32; o <<= 1) {
            int t = __shfl_up_sync(0xFFFFFFFFu, ws, o);
            if (lane >= o) ws += t;
        }
        warpsum[lane] = ws;
    }
    __syncthreads();
    int exc = v - s + (w > 0 ? warpsum[w - 1] : 0);
    if (tid == 1023) g_off[NN] = exc + s;
    int run = exc;
    for (int i = 0; i < CH; i++) {
        int n = b0 + i;
        if (n < NN) { g_off[n] = run; run += g_deg[n]; }
    }
}
__global__ void k_scatter(const int* __restrict__ src, const int* __restrict__ dst) {
    int i = blockIdx.x * blockDim.x + threadIdx.x;
    if (i >= NE) return;
    int d = dst[i];
    int p = atomicAdd(&g_cur[d], 1);
    g_csr_src[g_off[d] + p] = src[i];
}

// ---------------- one prep kernel: x->fp16, W1^T->fp16, W2^T->fp16 ----------------
#define PREP_X (NN * DC / 4)            // float4 chunks
#define PREP_W (F1C * DC)               // elements per W
__global__ void k_prep(const float* __restrict__ x, const float* __restrict__ W1,
                       const float* __restrict__ W2) {
    int i = blockIdx.x * blockDim.x + threadIdx.x;
    if (i < PREP_X) {
        int e = i * 4;
        float4 v = *(const float4*)&x[e];
        __half2 p0 = __floats2half2_rn(v.x, v.y);
        __half2 p1 = __floats2half2_rn(v.z, v.w);
        uint2 u; u.x = *(uint32_t*)&p0; u.y = *(uint32_t*)&p1;
        *(uint2*)&g_x16[e] = u;
    } else if (i < PREP_X + PREP_W) {
        int j = i - PREP_X;            // w1t[n*DC + k] = W1[k*F1C + n]
        int n = j / DC, k = j - n * DC;
        g_w1t[j] = __float2half(W1[(size_t)k * F1C + n]);
    } else if (i < PREP_X + 2 * PREP_W) {
        int j = i - PREP_X - PREP_W;   // w2t[n*F1C + k] = W2[k*DC + n]
        int n = j / F1C, k = j - n * F1C;
        g_w2t[j] = __float2half(W2[(size_t)k * DC + n]);
    }
}

// ---------------- fp16 HMMA GEMM, cp.async double-buffered ----------------
// C[M,N] (fp16) = A[M,K] @ B^T, B stored [N,K] fp16. Block 128x128, BK=32, 8 warps.
// Fused epilogue: el[n]=dot(C_row,al[h]), er likewise (fp32, h = blockIdx.x),
// written with stride ES. Direct half2 C stores (no smem staging).
__global__ void __launch_bounds__(256, 2)
k_gemm_mma(const __half* __restrict__ A, const __half* __restrict__ B,
           __half* __restrict__ C, const float* __restrict__ al, const float* __restrict__ ar,
           float* __restrict__ el, float* __restrict__ er, int M, int N, int K, int ES) {
    extern __shared__ char smem[];
    uint32_t sb = smem_u32(smem);
    int tid = threadIdx.x;
    int wid = tid >> 5, lane = tid & 31;
    int wm = wid >> 2, wn = wid & 3;
    int m0 = blockIdx.y * 128, n0 = blockIdx.x * 128;
    int h = blockIdx.x;

    float acc[4][4][4];
    #pragma unroll
    for (int i = 0; i < 4; i++)
        #pragma unroll
        for (int j = 0; j < 4; j++)
            #pragma unroll
            for (int q = 0; q < 4; q++) acc[i][j][q] = 0.f;

    int a_row = wm * 64 + (lane & 15);
    int a_coff = (lane >> 4) * 16;
    int b_row = wn * 32 + (lane & 7) + ((lane >> 4) & 1) * 8;
    int b_coff = ((lane >> 3) & 1) * 16;

    int nch = K >> 5;

    auto issue = [&](int c) {
        uint32_t stb = sb + (uint32_t)(c & 1) * STG;
        int k0 = c << 5;
        #pragma unroll
        for (int i = 0; i < 2; i++) {
            int ch = tid + i * 256;
            int r = ch >> 2, q = ch & 3;
            uint32_t so = stb + r * 80 + q * 16;
            int gm = m0 + r;
            int ok = (gm < M) ? 16 : 0;
            int rs = ok ? gm : 0;
            cp16p(so, &A[(size_t)rs * K + k0 + q * 8], ok);
            cp16(so + 10240, &B[(size_t)(n0 + r) * K + k0 + q * 8]);
        }
        asm volatile("cp.async.commit_group;" ::: "memory");
    };

    issue(0);
    for (int c = 0; c < nch; c++) {
        if (c + 1 < nch) {
            issue(c + 1);
            asm volatile("cp.async.wait_group 1;" ::: "memory");
        } else {
            asm volatile("cp.async.wait_group 0;" ::: "memory");
        }
        __syncthreads();
        uint32_t stb = sb + (uint32_t)(c & 1) * STG;
        #pragma unroll
        for (int ks = 0; ks < 2; ks++) {
            uint32_t kb = ks * 32;
            uint32_t af[4][4];
            #pragma unroll
            for (int mf = 0; mf < 4; mf++) {
                uint32_t ao = (a_row + mf * 16) * 80 + kb + a_coff;
                ldsm4(af[mf], stb + ao);
            }
            uint32_t bf[4][4];
            #pragma unroll
            for (int j = 0; j < 2; j++) {
                uint32_t bo = (b_row + j * 16) * 80 + kb + b_coff;
                ldsm4(bf[j * 2], stb + 10240 + bo);
            }
            #pragma unroll
            for (int mf = 0; mf < 4; mf++) {
                #pragma unroll
                for (int nf = 0; nf < 4; nf++) {
                    const uint32_t* b2p = &bf[(nf >> 1) * 2][(nf & 1) * 2];
                    mma16816h(acc[mf][nf], af[mf], b2p);
                }
            }
        }
        __syncthreads();
    }

    // ---- fused el/er: per-row dot partials into smem ----
    float* el_s = (float*)(smem + S_ELER);
    float* er_s = el_s + 128;
    if (tid < 128) { el_s[tid] = 0.f; er_s[tid] = 0.f; }
    __syncthreads();
    {
        float a0[4], a1[4], r0[4], r1[4];
        #pragma unroll
        for (int nf = 0; nf < 4; nf++) {
            int gc = h * DC + wn * 32 + nf * 8 + (lane & 3) * 2;
            a0[nf] = al[gc]; a1[nf] = al[gc + 1];
            r0[nf] = ar[gc]; r1[nf] = ar[gc + 1];
        }
        #pragma unroll
        for (int mf = 0; mf < 4; mf++) {
            float s0e = 0.f, s0r = 0.f, s1e = 0.f, s1r = 0.f;
            #pragma unroll
            for (int nf = 0; nf < 4; nf++) {
                s0e += acc[mf][nf][0] * a0[nf] + acc[mf][nf][1] * a1[nf];
                s0r += acc[mf][nf][0] * r0[nf] + acc[mf][nf][1] * r1[nf];
                s1e += acc[mf][nf][2] * a0[nf] + acc[mf][nf][3] * a1[nf];
                s1r += acc[mf][nf][2] * r0[nf] + acc[mf][nf][3] * r1[nf];
            }
            int row = wm * 64 + mf * 16 + (lane >> 2);
            atomicAdd(&el_s[row], s0e);
            atomicAdd(&er_s[row], s0r);
            atomicAdd(&el_s[row + 8], s1e);
            atomicAdd(&er_s[row + 8], s1r);
        }
    }

    // ---- direct C stores (half2 per fragment pair) ----
    #pragma unroll
    for (int mf = 0; mf < 4; mf++) {
        int r0 = m0 + wm * 64 + mf * 16 + (lane >> 2);
        #pragma unroll
        for (int nf = 0; nf < 4; nf++) {
            int col = n0 + wn * 32 + nf * 8 + (lane & 3) * 2;
            if (r0 < M) {
                __half2 p = __floats2half2_rn(acc[mf][nf][0], acc[mf][nf][1]);
                *(__half2*)&C[(size_t)r0 * N + col] = p;
            }
            if (r0 + 8 < M) {
                __half2 p = __floats2half2_rn(acc[mf][nf][2], acc[mf][nf][3]);
                *(__half2*)&C[(size_t)(r0 + 8) * N + col] = p;
            }
        }
    }
    __syncthreads();
    if (tid < 128 && m0 + tid < M) {
        el[(size_t)(m0 + tid) * ES + h] = el_s[tid];
        er[(size_t)(m0 + tid) * ES + h] = er_s[tid];
    }
}

// ---------------- layer-1 agg: one warp per dst, all 3 heads ----------------
__global__ void k_agg1(const __half* __restrict__ f, const float* __restrict__ el4,
                       const float* __restrict__ er4, const float* __restrict__ b,
                       __half* __restrict__ outH) {
    int d = (blockIdx.x * blockDim.x + threadIdx.x) >> 5;
    int lane = threadIdx.x & 31;
    if (d >= NN) return;
    int off0 = g_off[d];
    int deg = g_off[d + 1] - off0;
    float4 erv = *(const float4*)&er4[(size_t)d * 4];

    float acc[3][4];
    #pragma unroll
    for (int h = 0; h < 3; h++)
        #pragma unroll
        for (int q = 0; q < 4; q++) acc[h][q] = 0.f;
    float den[3] = {0.f, 0.f, 0.f};

    if (deg <= 32) {
        int s = 0;
        float v[3] = {-3.0e38f, -3.0e38f, -3.0e38f};
        if (lane < deg) {
            s = g_csr_src[off0 + lane];
            float4 ev = *(const float4*)&el4[(size_t)s * 4];
            float t0 = ev.x + erv.x, t1 = ev.y + erv.y, t2 = ev.z + erv.z;
            v[0] = t0 > 0.f ? t0 : NEG_SLOPE * t0;
            v[1] = t1 > 0.f ? t1 : NEG_SLOPE * t1;
            v[2] = t2 > 0.f ? t2 : NEG_SLOPE * t2;
        }
        float ex[3];
        #pragma unroll
        for (int h = 0; h < 3; h++) {
            float mx = v[h];
            #pragma unroll
            for (int o = 16; o > 0; o >>= 1)
                mx = fmaxf(mx, __shfl_xor_sync(0xFFFFFFFFu, mx, o));
            ex[h] = (lane < deg) ? __expf(v[h] - mx) : 0.f;
            float dd = ex[h];
            #pragma unroll
            for (int o = 16; o > 0; o >>= 1)
                dd += __shfl_xor_sync(0xFFFFFFFFu, dd, o);
            den[h] = dd;
        }
        #pragma unroll 2
        for (int j = 0; j < deg; j++) {
            int sj  = __shfl_sync(0xFFFFFFFFu, s, j);
            float e0 = __shfl_sync(0xFFFFFFFFu, ex[0], j);
            float e1 = __shfl_sync(0xFFFFFFFFu, ex[1], j);
            float e2 = __shfl_sync(0xFFFFFFFFu, ex[2], j);
            size_t base = (size_t)sj * F1C + lane * 4;
            uint2 u0 = *(const uint2*)&f[base];
            uint2 u1 = *(const uint2*)&f[base + DC];
            uint2 u2 = *(const uint2*)&f[base + 2 * DC];
            float2 p;
            p = __half22float2(*(__half2*)&u0.x);
            acc[0][0] = fmaf(e0, p.x, acc[0][0]); acc[0][1] = fmaf(e0, p.y, acc[0][1]);
            p = __half22float2(*(__half2*)&u0.y);
            acc[0][2] = fmaf(e0, p.x, acc[0][2]); acc[0][3] = fmaf(e0, p.y, acc[0][3]);
            p = __half22float2(*(__half2*)&u1.x);
            acc[1][0] = fmaf(e1, p.x, acc[1][0]); acc[1][1] = fmaf(e1, p.y, acc[1][1]);
            p = __half22float2(*(__half2*)&u1.y);
            acc[1][2] = fmaf(e1, p.x, acc[1][2]); acc[1][3] = fmaf(e1, p.y, acc[1][3]);
            p = __half22float2(*(__half2*)&u2.x);
            acc[2][0] = fmaf(e2, p.x, acc[2][0]); acc[2][1] = fmaf(e2, p.y, acc[2][1]);
            p = __half22float2(*(__half2*)&u2.y);
            acc[2][2] = fmaf(e2, p.x, acc[2][2]); acc[2][3] = fmaf(e2, p.y, acc[2][3]);
        }
    } else {
        // fallback: strided max pass then serial accumulate
        float mx[3] = {-3.0e38f, -3.0e38f, -3.0e38f};
        for (int j = lane; j < deg; j += 32) {
            int s = g_csr_src[off0 + j];
            float4 ev = *(const float4*)&el4[(size_t)s * 4];
            float t0 = ev.x + erv.x, t1 = ev.y + erv.y, t2 = ev.z + erv.z;
            t0 = t0 > 0.f ? t0 : NEG_SLOPE * t0;
            t1 = t1 > 0.f ? t1 : NEG_SLOPE * t1;
            t2 = t2 > 0.f ? t2 : NEG_SLOPE * t2;
            mx[0] = fmaxf(mx[0], t0); mx[1] = fmaxf(mx[1], t1); mx[2] = fmaxf(mx[2], t2);
        }
        #pragma unroll
        for (int h = 0; h < 3; h++)
            #pragma unroll
            for (int o = 16; o > 0; o >>= 1)
                mx[h] = fmaxf(mx[h], __shfl_xor_sync(0xFFFFFFFFu, mx[h], o));
        for (int j = 0; j < deg; j++) {
            int s = g_csr_src[off0 + j];
            float4 ev = *(const float4*)&el4[(size_t)s * 4];
            float t0 = ev.x + erv.x, t1 = ev.y + erv.y, t2 = ev.z + erv.z;
            t0 = t0 > 0.f ? t0 : NEG_SLOPE * t0;
            t1 = t1 > 0.f ? t1 : NEG_SLOPE * t1;
            t2 = t2 > 0.f ? t2 : NEG_SLOPE * t2;
            float e0 = __expf(t0 - mx[0]);
            float e1 = __expf(t1 - mx[1]);
            float e2 = __expf(t2 - mx[2]);
            den[0] += e0; den[1] += e1; den[2] += e2;
            size_t base = (size_t)s * F1C + lane * 4;
            uint2 u0 = *(const uint2*)&f[base];
            uint2 u1 = *(const uint2*)&f[base + DC];
            uint2 u2 = *(const uint2*)&f[base + 2 * DC];
            float2 p;
            p = __half22float2(*(__half2*)&u0.x);
            acc[0][0] = fmaf(e0, p.x, acc[0][0]); acc[0][1] = fmaf(e0, p.y, acc[0][1]);
            p = __half22float2(*(__half2*)&u0.y);
            acc[0][2] = fmaf(e0, p.x, acc[0][2]); acc[0][3] = fmaf(e0, p.y, acc[0][3]);
            p = __half22float2(*(__half2*)&u1.x);
            acc[1][0] = fmaf(e1, p.x, acc[1][0]); acc[1][1] = fmaf(e1, p.y, acc[1][1]);
            p = __half22float2(*(__half2*)&u1.y);
            acc[1][2] = fmaf(e1, p.x, acc[1][2]); acc[1][3] = fmaf(e1, p.y, acc[1][3]);
            p = __half22float2(*(__half2*)&u2.x);
            acc[2][0] = fmaf(e2, p.x, acc[2][0]); acc[2][1] = fmaf(e2, p.y, acc[2][1]);
            p = __half22float2(*(__half2*)&u2.y);
            acc[2][2] = fmaf(e2, p.x, acc[2][2]); acc[2][3] = fmaf(e2, p.y, acc[2][3]);
        }
    }

    // epilogue: bias + elu + fp16 store per head
    #pragma unroll
    for (int h = 0; h < 3; h++) {
        float inv = 1.f / (den[h] > 0.f ? den[h] : 1.f);
        float4 bb = *(const float4*)&b[h * DC + lane * 4];
        float rx = acc[h][0] * inv + bb.x;
        float ry = acc[h][1] * inv + bb.y;
        float rz = acc[h][2] * inv + bb.z;
        float rw = acc[h][3] * inv + bb.w;
        rx = rx > 0.f ? rx : expm1f(rx);
        ry = ry > 0.f ? ry : expm1f(ry);
        rz = rz > 0.f ? rz : expm1f(rz);
        rw = rw > 0.f ? rw : expm1f(rw);
        __half2 p0 = __floats2half2_rn(rx, ry);
        __half2 p1 = __floats2half2_rn(rz, rw);
        uint2 u; u.x = *(uint32_t*)&p0; u.y = *(uint32_t*)&p1;
        *(uint2*)&outH[(size_t)d * F1C + h * DC + lane * 4] = u;
    }
}

// ---------------- layer-2 agg fused with graph mean-pool accumulation ----------------
__global__ void k_agg_pool(const __half* __restrict__ f, const float* __restrict__ el,
                           const float* __restrict__ er, const float* __restrict__ b,
                           const int* __restrict__ gids) {
    __shared__ float pacc[DC];
    __shared__ int uni;
    int tid = threadIdx.x;
    int wid = tid >> 5, lane = tid & 31;
    int d0 = blockIdx.x * 8;
    int d = d0 + wid;
    if (tid == 0) uni = (gids[d0] == gids[d0 + 7]) ? 1 : 0;
    if (tid < DC) pacc[tid] = 0.f;
    __syncthreads();

    int off0 = g_off[d];
    int deg = g_off[d + 1] - off0;
    float erd = er[d];

    float4 acc = make_float4(0.f, 0.f, 0.f, 0.f);
    float den = 0.f;
    if (deg <= 32) {
        int s = 0;
        float v = -3.0e38f;
        if (lane < deg) {
            s = g_csr_src[off0 + lane];
            v = el[s] + erd;
            v = v > 0.f ? v : NEG_SLOPE * v;
        }
        float mx = v;
        #pragma unroll
        for (int o = 16; o > 0; o >>= 1)
            mx = fmaxf(mx, __shfl_xor_sync(0xFFFFFFFFu, mx, o));
        float ex = (lane < deg) ? __expf(v - mx) : 0.f;
        float dd = ex;
        #pragma unroll
        for (int o = 16; o > 0; o >>= 1)
            dd += __shfl_xor_sync(0xFFFFFFFFu, dd, o);
        den = dd;
        #pragma unroll 4
        for (int j = 0; j < deg; j++) {
            float exj = __shfl_sync(0xFFFFFFFFu, ex, j);
            int   sj  = __shfl_sync(0xFFFFFFFFu, s, j);
            uint2 u = *(const uint2*)&f[(size_t)sj * DC + lane * 4];
            float2 p0 = __half22float2(*(__half2*)&u.x);
            float2 p1 = __half22float2(*(__half2*)&u.y);
            acc.x = fmaf(exj, p0.x, acc.x);
            acc.y = fmaf(exj, p0.y, acc.y);
            acc.z = fmaf(exj, p1.x, acc.z);
            acc.w = fmaf(exj, p1.y, acc.w);
        }
    } else {
        float mx = -3.0e38f;
        for (int j = lane; j < deg; j += 32) {
            int s = g_csr_src[off0 + j];
            float v = el[s] + erd;
            v = v > 0.f ? v : NEG_SLOPE * v;
            mx = fmaxf(mx, v);
        }
        #pragma unroll
        for (int o = 16; o > 0; o >>= 1)
            mx = fmaxf(mx, __shfl_xor_sync(0xFFFFFFFFu, mx, o));
        for (int j = 0; j < deg; j++) {
            int s = g_csr_src[off0 + j];
            float v = el[s] + erd;
            v = v > 0.f ? v : NEG_SLOPE * v;
            float ex = __expf(v - mx);
            den += ex;
            uint2 u = *(const uint2*)&f[(size_t)s * DC + lane * 4];
            float2 p0 = __half22float2(*(__half2*)&u.x);
            float2 p1 = __half22float2(*(__half2*)&u.y);
            acc.x = fmaf(ex, p0.x, acc.x);
            acc.y = fmaf(ex, p0.y, acc.y);
            acc.z = fmaf(ex, p1.x, acc.z);
            acc.w = fmaf(ex, p1.y, acc.w);
        }
    }

    float inv = 1.f / (den > 0.f ? den : 1.f);
    float4 bb = *(const float4*)&b[lane * 4];
    float4 r;
    r.x = acc.x * inv + bb.x;
    r.y = acc.y * inv + bb.y;
    r.z = acc.z * inv + bb.z;
    r.w = acc.w * inv + bb.w;

    if (uni) {
        atomicAdd(&pacc[lane * 4 + 0], r.x);
        atomicAdd(&pacc[lane * 4 + 1], r.y);
        atomicAdd(&pacc[lane * 4 + 2], r.z);
        atomicAdd(&pacc[lane * 4 + 3], r.w);
    } else {
        int g = gids[d];
        atomicAdd(&g_sums[g * DC + lane * 4 + 0], r.x);
        atomicAdd(&g_sums[g * DC + lane * 4 + 1], r.y);
        atomicAdd(&g_sums[g * DC + lane * 4 + 2], r.z);
        atomicAdd(&g_sums[g * DC + lane * 4 + 3], r.w);
    }
    __syncthreads();
    if (uni && tid < DC) atomicAdd(&g_sums[gids[d0] * DC + tid], pacc[tid]);
}

// ---------------- output: relu((sums/cnt) @ linW + linb) ----------------
__global__ void k_out(const float* __restrict__ linW, const float* __restrict__ linb,
                      float* __restrict__ out) {
    int g = blockIdx.x;
    int c = threadIdx.x;
    __shared__ float hg[DC];
    float cnt = g_cnt[g];
    if (cnt < 1.f) cnt = 1.f;
    hg[c] = g_sums[g * DC + c] / cnt;
    __syncthreads();
    float acc = linb[c];
    #pragma unroll 8
    for (int k = 0; k < DC; k++)
        acc = fmaf(hg[k], linW[k * DC + c], acc);
    out[g * DC + c] = acc > 0.f ? acc : 0.f;
}

// ---------------- launch ----------------
extern "C" void kernel_launch(void* const* d_in, const int* in_sizes, int n_in,
                              void* d_out, int out_size) {
    const float* x    = (const float*)d_in[0];
    const int*   src  = (const int*)  d_in[1];
    const int*   dst  = (const int*)  d_in[2];
    const int*   gids = (const int*)  d_in[3];
    const float* W1   = (const float*)d_in[4];
    const float* al1  = (const float*)d_in[5];
    const float* ar1  = (const float*)d_in[6];
    const float* b1   = (const float*)d_in[7];
    const float* W2   = (const float*)d_in[8];
    const float* al2  = (const float*)d_in[9];
    const float* ar2  = (const float*)d_in[10];
    const float* b2   = (const float*)d_in[11];
    const float* linW = (const float*)d_in[12];
    const float* linb = (const float*)d_in[13];
    float* out = (float*)d_out;

    static cudaStream_t s1 = nullptr;
    static cudaEvent_t evFork = nullptr, evJoin = nullptr;
    if (!s1) {
        cudaStreamCreateWithFlags(&s1, cudaStreamNonBlocking);
        cudaEventCreateWithFlags(&evFork, cudaEventDisableTiming);
        cudaEventCreateWithFlags(&evJoin, cudaEventDisableTiming);
        cudaFuncSetAttribute(k_gemm_mma, cudaFuncAttributeMaxDynamicSharedMemorySize, SM_GEMM);
    }

    void *p_f1, *p_el1, *p_er1, *p_x16, *p_h16, *p_w1t, *p_w2t;
    void *p_f2, *p_el2, *p_er2;
    cudaGetSymbolAddress(&p_f1,  g_f1);
    cudaGetSymbolAddress(&p_el1, g_el1);
    cudaGetSymbolAddress(&p_er1, g_er1);
    cudaGetSymbolAddress(&p_x16, g_x16);
    cudaGetSymbolAddress(&p_h16, g_h16);
    cudaGetSymbolAddress(&p_w1t, g_w1t);
    cudaGetSymbolAddress(&p_w2t, g_w2t);
    cudaGetSymbolAddress(&p_f2,  g_f2);
    cudaGetSymbolAddress(&p_el2, g_el2);
    cudaGetSymbolAddress(&p_er2, g_er2);

    // ---- fork: CSR branch on s1, GEMM-prep branch on stream 0 ----
    cudaEventRecord(evFork, 0);
    cudaStreamWaitEvent(s1, evFork, 0);

    // Branch A (s1): CSR build + pool-count init
    k_zero_small<<<(NN + 255) / 256, 256, 0, s1>>>();
    k_deg<<<(NE + 255) / 256, 256, 0, s1>>>(dst, gids);
    k_scan<<<1, 1024, 0, s1>>>();
    k_scatter<<<(NE + 255) / 256, 256, 0, s1>>>(src, dst);
    cudaEventRecord(evJoin, s1);

    // Branch B (stream 0): prep + GEMM1
    {
        int total = PREP_X + 2 * PREP_W;
        k_prep<<<(total + 255) / 256, 256>>>(x, W1, W2);
    }

    int mtiles = (NN + 127) / 128;   // 157
    {
        dim3 grid(F1C / 128, mtiles);
        k_gemm_mma<<<grid, 256, SM_GEMM>>>(
            (const __half*)p_x16, (const __half*)p_w1t,
            (__half*)p_f1, al1, ar1, (float*)p_el1, (float*)p_er1,
            NN, F1C, DC, 4);
    }

    // ---- join: agg1 needs CSR + GEMM1 ----
    cudaStreamWaitEvent(0, evJoin, 0);
    k_agg1<<<(NN * 32 + 255) / 256, 256>>>(
        (const __half*)p_f1, (const float*)p_el1, (const float*)p_er1, b1,
        (__half*)p_h16);

    // ---- Layer 2 ----
    {
        dim3 grid(1, mtiles);
        k_gemm_mma<<<grid, 256, SM_GEMM>>>(
            (const __half*)p_h16, (const __half*)p_w2t,
            (__half*)p_f2, al2, ar2, (float*)p_el2, (float*)p_er2,
            NN, DC, F1C, 1);
    }
    k_agg_pool<<<NN / 8, 256>>>((const __half*)p_f2, (const float*)p_el2,
                                (const float*)p_er2, b2, gids);

    // ---- readout ----
    k_out<<<NG, DC>>>(linW, linb, out);
}